// round 1
// baseline (speedup 1.0000x reference)
#include <cuda_runtime.h>
#include <stdint.h>

#define BB   8
#define NA   3
#define NC   80
#define HH   160
#define WW   160
#define HW   (HH*WW)        // 25600
#define NN   (NA*HW)        // 76800
#define TOPK 100
#define NBINS 2048
#define CAP  1024

// ---------------- device scratch (no allocations allowed) ----------------
__device__ float    g_scores[BB*NN];
__device__ uint8_t  g_cls[BB*NN];
__device__ int      g_hist[BB*NBINS];
__device__ int      g_topidx[BB*TOPK];

__device__ __forceinline__ float sigmoidf_(float x) {
    return 1.0f / (1.0f + expf(-x));
}

// ---------------- kernel 0: zero histograms ----------------
__global__ void zero_hist_kernel() {
    int i = blockIdx.x * blockDim.x + threadIdx.x;
    if (i < BB * NBINS) g_hist[i] = 0;
}

// ---------------- kernel 1: per-cell score + argmax class + level-1 hist ----------------
__global__ void __launch_bounds__(256) score_kernel(const float* __restrict__ obj,
                                                    const float* __restrict__ quality,
                                                    const float* __restrict__ cls) {
    int t = blockIdx.x * blockDim.x + threadIdx.x;   // cell index over B*N
    if (t >= BB * NN) return;
    int b   = t / NN;
    int r   = t - b * NN;          // a*HW + pix
    int a   = r / HW;
    int pix = r - a * HW;

    const float* cbase = cls + ((size_t)(b * NA + a) * NC) * HW + pix;
    float m = -1e30f;
    int   mi = 0;
    #pragma unroll 8
    for (int c = 0; c < NC; c++) {
        float v = cbase[(size_t)c * HW];
        if (v > m) { m = v; mi = c; }
    }

    int oq = (b * NA + a) * HW + pix;
    float s = sigmoidf_(obj[oq]) * sigmoidf_(quality[oq]) * sigmoidf_(m);

    g_scores[t] = s;
    g_cls[t]    = (uint8_t)mi;
    unsigned bits = __float_as_uint(s);              // s in (0,1) -> sign bit 0
    atomicAdd(&g_hist[b * NBINS + (bits >> 21)], 1);
}

// ---------------- kernel 2: per-batch top-100 (radix refine + bitonic) ----------------
__global__ void __launch_bounds__(1024) topk_kernel(float* __restrict__ out) {
    __shared__ int                sh[NBINS];
    __shared__ unsigned long long buf[CAP];
    __shared__ int s_cnt, s_t, s_chi, s_u;

    int b   = blockIdx.x;
    int tid = threadIdx.x;

    // level-1 suffix scan (find coarse bin containing rank-100)
    for (int i = tid; i < NBINS; i += 1024) sh[i] = g_hist[b * NBINS + i];
    __syncthreads();
    if (tid == 0) {
        int cum = 0, tt = 0, chi = 0;
        for (int i = NBINS - 1; i >= 0; i--) {
            int c = sh[i];
            if (cum + c >= TOPK) { tt = i; chi = cum; break; }
            cum += c;
        }
        s_t = tt; s_chi = chi;
    }
    __syncthreads();
    int t1 = s_t, chi = s_chi;

    // level-2 histogram within boundary bin
    for (int i = tid; i < NBINS; i += 1024) sh[i] = 0;
    __syncthreads();
    const float* sc = g_scores + (size_t)b * NN;
    for (int i = tid; i < NN; i += 1024) {
        unsigned bits = __float_as_uint(sc[i]);
        if ((int)(bits >> 21) == t1) atomicAdd(&sh[(bits >> 10) & (NBINS - 1)], 1);
    }
    __syncthreads();
    if (tid == 0) {
        int cum = chi, u = 0;
        for (int i = NBINS - 1; i >= 0; i--) {
            int c = sh[i];
            if (cum + c >= TOPK) { u = i; break; }
            cum += c;
        }
        s_u = u;
        s_cnt = 0;
    }
    __syncthreads();
    unsigned thr22 = (((unsigned)t1) << 11) | (unsigned)s_u;

    // collect candidates >= 22-bit threshold prefix
    for (int i = tid; i < NN; i += 1024) {
        unsigned bits = __float_as_uint(sc[i]);
        if ((bits >> 10) >= thr22) {
            int p = atomicAdd(&s_cnt, 1);
            if (p < CAP)
                buf[p] = (((unsigned long long)bits) << 17) |
                         (unsigned long long)(0x1FFFFu - (unsigned)i);
        }
    }
    __syncthreads();
    int cnt = s_cnt;
    for (int i = tid; i < CAP; i += 1024)
        if (i >= cnt) buf[i] = 0ULL;
    __syncthreads();

    // bitonic sort 1024 u64 keys, descending
    for (int k = 2; k <= CAP; k <<= 1) {
        for (int j = k >> 1; j > 0; j >>= 1) {
            int ixj = tid ^ j;
            if (ixj > tid) {
                bool up = ((tid & k) == 0);     // keep larger at lower index
                unsigned long long A = buf[tid], Bv = buf[ixj];
                bool sw = up ? (A < Bv) : (A > Bv);
                if (sw) { buf[tid] = Bv; buf[ixj] = A; }
            }
            __syncthreads();
        }
    }

    if (tid < TOPK) {
        unsigned long long key = buf[tid];
        int   idx = 0x1FFFF - (int)(key & 0x1FFFF);
        float s   = __uint_as_float((unsigned)(key >> 17));
        g_topidx[b * TOPK + tid] = idx;
        out[((b * TOPK) + tid) * 6 + 0] = s;
    }
}

// ---------------- kernel 3: decode boxes for selected cells ----------------
__global__ void gather_kernel(const float* __restrict__ box,
                              const float* __restrict__ anchors,
                              float* __restrict__ out) {
    int t = blockIdx.x * blockDim.x + threadIdx.x;
    if (t >= BB * TOPK) return;
    int b = t / TOPK;
    int idx = g_topidx[t];
    int a   = idx / HW;
    int pix = idx - a * HW;
    int h   = pix / WW;
    int w   = pix - h * WW;

    const float* bb = box + ((size_t)(b * NA + a) * 4) * HW + pix;
    float tx = bb[0];
    float ty = bb[HW];
    float tw = bb[2 * HW];
    float th = bb[3 * HW];

    float cx = (sigmoidf_(tx) + (float)w) / (float)WW;
    float cy = (sigmoidf_(ty) + (float)h) / (float)HH;
    // custom softplus: relu(x) + log1p(exp(-|x|))
    float spw = fmaxf(tw, 0.0f) + log1pf(expf(-fabsf(tw)));
    float sph = fmaxf(th, 0.0f) + log1pf(expf(-fabsf(th)));
    float bw = anchors[a * 2 + 0] * spw;
    float bh = anchors[a * 2 + 1] * sph;
    float clsv = (float)g_cls[(size_t)b * NN + idx];

    float* o = out + (size_t)t * 6;
    o[1] = clsv;
    o[2] = cx;
    o[3] = cy;
    o[4] = bw;
    o[5] = bh;
}

// ---------------- launch ----------------
extern "C" void kernel_launch(void* const* d_in, const int* in_sizes, int n_in,
                              void* d_out, int out_size) {
    const float* box     = (const float*)d_in[0];
    const float* obj     = (const float*)d_in[1];
    const float* quality = (const float*)d_in[2];
    const float* cls     = (const float*)d_in[3];
    const float* anchors = (const float*)d_in[4];
    float* out = (float*)d_out;

    zero_hist_kernel<<<(BB * NBINS + 255) / 256, 256>>>();
    score_kernel<<<(BB * NN + 255) / 256, 256>>>(obj, quality, cls);
    topk_kernel<<<BB, 1024>>>(out);
    gather_kernel<<<(BB * TOPK + 255) / 256, 256>>>(box, anchors, out);
}

// round 2
// speedup vs baseline: 2.1998x; 2.1998x over previous
#include <cuda_runtime.h>
#include <stdint.h>

#define BB   8
#define NA   3
#define NC   80
#define HH   160
#define WW   160
#define HW   (HH*WW)        // 25600
#define NN   (NA*HW)        // 76800
#define TOPK 100
#define NBINS 2048
#define CAP  1024

// ---------------- device scratch (no allocations allowed) ----------------
__device__ float    g_scores[BB*NN];
__device__ uint8_t  g_cls[BB*NN];

__device__ __forceinline__ float sigmoidf_(float x) {
    return 1.0f / (1.0f + expf(-x));
}

// ---------------- kernel 1: per-cell score + argmax class (pure streaming) ----------------
// Each thread handles 4 consecutive pixels (float4 loads per class plane).
__global__ void __launch_bounds__(256) score_kernel(const float* __restrict__ obj,
                                                    const float* __restrict__ quality,
                                                    const float* __restrict__ cls) {
    int t  = blockIdx.x * blockDim.x + threadIdx.x;    // quad index over B*N/4
    int c0 = t * 4;                                    // base cell index
    if (c0 >= BB * NN) return;
    int b   = c0 / NN;
    int r   = c0 - b * NN;
    int a   = r / HW;
    int pix = r - a * HW;                              // multiple of 4

    const float4* cbase = (const float4*)(cls + ((size_t)(b * NA + a) * NC) * HW + pix);
    float m0 = -1e30f, m1 = -1e30f, m2 = -1e30f, m3 = -1e30f;
    int   i0 = 0, i1 = 0, i2 = 0, i3 = 0;
    #pragma unroll 8
    for (int c = 0; c < NC; c++) {
        float4 v = cbase[c * (HW / 4)];
        if (v.x > m0) { m0 = v.x; i0 = c; }
        if (v.y > m1) { m1 = v.y; i1 = c; }
        if (v.z > m2) { m2 = v.z; i2 = c; }
        if (v.w > m3) { m3 = v.w; i3 = c; }
    }

    int oq = (b * NA + a) * HW + pix;
    float4 ov = *(const float4*)(obj + oq);
    float4 qv = *(const float4*)(quality + oq);

    float4 s;
    s.x = sigmoidf_(ov.x) * sigmoidf_(qv.x) * sigmoidf_(m0);
    s.y = sigmoidf_(ov.y) * sigmoidf_(qv.y) * sigmoidf_(m1);
    s.z = sigmoidf_(ov.z) * sigmoidf_(qv.z) * sigmoidf_(m2);
    s.w = sigmoidf_(ov.w) * sigmoidf_(qv.w) * sigmoidf_(m3);

    *(float4*)(g_scores + c0) = s;
    uchar4 cl = make_uchar4((uint8_t)i0, (uint8_t)i1, (uint8_t)i2, (uint8_t)i3);
    *(uchar4*)(g_cls + c0) = cl;
}

// ---------------- kernel 2: per-batch top-100 + box decode ----------------
__global__ void __launch_bounds__(1024) topk_kernel(const float* __restrict__ box,
                                                    const float* __restrict__ anchors,
                                                    float* __restrict__ out) {
    __shared__ int                sh[NBINS];
    __shared__ unsigned long long buf[CAP];
    __shared__ int s_cnt, s_t, s_chi, s_u;

    int b   = blockIdx.x;
    int tid = threadIdx.x;
    const float* sc = g_scores + (size_t)b * NN;

    // ---- pass A: level-1 histogram (top 11 bits of score) in shared ----
    sh[tid] = 0; sh[tid + 1024] = 0;
    __syncthreads();
    for (int i = tid; i < NN; i += 1024) {
        unsigned bits = __float_as_uint(sc[i]);        // scores in (0,1): sign=0
        atomicAdd(&sh[bits >> 21], 1);
    }
    __syncthreads();

    // ---- parallel inclusive suffix scan (Hillis-Steele) ----
    #pragma unroll
    for (int d = 1; d < NBINS; d <<= 1) {
        int v0 = (tid + d < NBINS) ? sh[tid + d] : 0;
        int v1 = (tid + 1024 + d < NBINS) ? sh[tid + 1024 + d] : 0;
        __syncthreads();
        sh[tid] += v0;
        sh[tid + 1024] += v1;
        __syncthreads();
    }
    // crossing bin: largest i with S[i] >= TOPK
    {
        int i = tid;
        if (sh[i] >= TOPK && (i == NBINS - 1 || sh[i + 1] < TOPK)) { s_t = i; s_chi = (i < NBINS - 1) ? sh[i + 1] : 0; }
        i = tid + 1024;
        if (sh[i] >= TOPK && (i == NBINS - 1 || sh[i + 1] < TOPK)) { s_t = i; s_chi = (i < NBINS - 1) ? sh[i + 1] : 0; }
    }
    __syncthreads();
    int t1 = s_t, chi = s_chi;

    // ---- pass B: level-2 histogram (next 11 bits) within boundary bin ----
    sh[tid] = 0; sh[tid + 1024] = 0;
    __syncthreads();
    for (int i = tid; i < NN; i += 1024) {
        unsigned bits = __float_as_uint(sc[i]);
        if ((int)(bits >> 21) == t1) atomicAdd(&sh[(bits >> 10) & (NBINS - 1)], 1);
    }
    __syncthreads();
    #pragma unroll
    for (int d = 1; d < NBINS; d <<= 1) {
        int v0 = (tid + d < NBINS) ? sh[tid + d] : 0;
        int v1 = (tid + 1024 + d < NBINS) ? sh[tid + 1024 + d] : 0;
        __syncthreads();
        sh[tid] += v0;
        sh[tid + 1024] += v1;
        __syncthreads();
    }
    {
        int i = tid;
        if (chi + sh[i] >= TOPK && (i == NBINS - 1 || chi + sh[i + 1] < TOPK)) s_u = i;
        i = tid + 1024;
        if (chi + sh[i] >= TOPK && (i == NBINS - 1 || chi + sh[i + 1] < TOPK)) s_u = i;
        if (tid == 0) s_cnt = 0;
    }
    __syncthreads();
    unsigned thr22 = (((unsigned)t1) << 11) | (unsigned)s_u;

    // ---- pass C: collect candidates >= 22-bit threshold prefix ----
    for (int i = tid; i < NN; i += 1024) {
        unsigned bits = __float_as_uint(sc[i]);
        if ((bits >> 10) >= thr22) {
            int p = atomicAdd(&s_cnt, 1);
            if (p < CAP)
                buf[p] = (((unsigned long long)bits) << 17) |
                         (unsigned long long)(0x1FFFFu - (unsigned)i);
        }
    }
    __syncthreads();
    int cnt = s_cnt;
    if (tid >= cnt) buf[tid] = 0ULL;   // CAP == blockDim
    __syncthreads();

    // ---- bitonic sort 1024 u64 keys, descending ----
    for (int k = 2; k <= CAP; k <<= 1) {
        for (int j = k >> 1; j > 0; j >>= 1) {
            int ixj = tid ^ j;
            if (ixj > tid) {
                bool up = ((tid & k) == 0);
                unsigned long long A = buf[tid], Bv = buf[ixj];
                bool sw = up ? (A < Bv) : (A > Bv);
                if (sw) { buf[tid] = Bv; buf[ixj] = A; }
            }
            __syncthreads();
        }
    }

    // ---- decode boxes for the 100 winners (fused gather) ----
    if (tid < TOPK) {
        unsigned long long key = buf[tid];
        int   idx = 0x1FFFF - (int)(key & 0x1FFFF);
        float s   = __uint_as_float((unsigned)(key >> 17));

        int a   = idx / HW;
        int pix = idx - a * HW;
        int h   = pix / WW;
        int w   = pix - h * WW;

        const float* bb = box + ((size_t)(b * NA + a) * 4) * HW + pix;
        float tx = bb[0];
        float ty = bb[HW];
        float tw = bb[2 * HW];
        float th = bb[3 * HW];

        float cx = (sigmoidf_(tx) + (float)w) / (float)WW;
        float cy = (sigmoidf_(ty) + (float)h) / (float)HH;
        float spw = fmaxf(tw, 0.0f) + log1pf(expf(-fabsf(tw)));
        float sph = fmaxf(th, 0.0f) + log1pf(expf(-fabsf(th)));
        float bw = anchors[a * 2 + 0] * spw;
        float bh = anchors[a * 2 + 1] * sph;
        float clsv = (float)g_cls[(size_t)b * NN + idx];

        float* o = out + ((size_t)b * TOPK + tid) * 6;
        o[0] = s;
        o[1] = clsv;
        o[2] = cx;
        o[3] = cy;
        o[4] = bw;
        o[5] = bh;
    }
}

// ---------------- launch ----------------
extern "C" void kernel_launch(void* const* d_in, const int* in_sizes, int n_in,
                              void* d_out, int out_size) {
    const float* box     = (const float*)d_in[0];
    const float* obj     = (const float*)d_in[1];
    const float* quality = (const float*)d_in[2];
    const float* cls     = (const float*)d_in[3];
    const float* anchors = (const float*)d_in[4];
    float* out = (float*)d_out;

    score_kernel<<<(BB * NN / 4 + 255) / 256, 256>>>(obj, quality, cls);
    topk_kernel<<<BB, 1024>>>(box, anchors, out);
}